// round 2
// baseline (speedup 1.0000x reference)
#include <cuda_runtime.h>
#include <math.h>

#define HID   768
#define SEQ   4096
#define BATCH 4
#define MTOT  (BATCH*SEQ)   // 16384

#define BM 128
#define BN 128
#define BK 16
#define PADA 20    // [row][k] tile stride (conflict-free fragment reads)
#define PADB 136   // [k][n] tile stride for ABN B operand

// ---------------- scratch (allocation-free: __device__ globals) ----------------
__device__ float g_q[(size_t)MTOT * HID];
__device__ float g_k[(size_t)MTOT * HID];
__device__ float g_v[(size_t)MTOT * HID];
__device__ float g_s[(size_t)BATCH * SEQ * SEQ];   // 256 MB scores

// ---------------- helpers ----------------
__device__ __forceinline__ unsigned f2tf(float x) {
    unsigned y;
    asm("cvt.rna.tf32.f32 %0, %1;" : "=r"(y) : "f"(x));
    return y;
}

__device__ __forceinline__ void mma8(float* c, const unsigned* a, unsigned b0, unsigned b1) {
    asm volatile(
        "mma.sync.aligned.m16n8k8.row.col.f32.tf32.tf32.f32 "
        "{%0,%1,%2,%3}, {%4,%5,%6,%7}, {%8,%9}, {%0,%1,%2,%3};"
        : "+f"(c[0]), "+f"(c[1]), "+f"(c[2]), "+f"(c[3])
        : "r"(a[0]), "r"(a[1]), "r"(a[2]), "r"(a[3]), "r"(b0), "r"(b1));
}

__device__ __forceinline__ float4 conv4(float4 v) {
    float4 w;
    w.x = __uint_as_float(f2tf(v.x));
    w.y = __uint_as_float(f2tf(v.y));
    w.z = __uint_as_float(f2tf(v.z));
    w.w = __uint_as_float(f2tf(v.w));
    return w;
}

// ---------------- C = alpha * A * B^T (+bias), A[M,K] rm, Bt[N,K] rm ----------------
__device__ __forceinline__ void gemm_abt_body(
    const float* __restrict__ A, const float* __restrict__ Bt,
    float* __restrict__ C, const float* __restrict__ bias,
    int K, int lda, int ldb, int ldc, float alpha)
{
    extern __shared__ float smem[];
    float* As = smem;                 // [2][BM*PADA]
    float* Bs = smem + 2 * BM * PADA; // [2][BN*PADA]

    const int tid  = threadIdx.x;
    const int lane = tid & 31;
    const int warp = tid >> 5;
    const int gid  = lane >> 2;   // 0..7
    const int tig  = lane & 3;    // 0..3
    const int wm   = (warp & 1) * 64;   // 2 warps in M
    const int wn   = (warp >> 1) * 32;  // 4 warps in N
    const int m0 = blockIdx.x * BM, n0 = blockIdx.y * BN;

    float acc[4][4][4];
#pragma unroll
    for (int i = 0; i < 4; i++)
#pragma unroll
        for (int j = 0; j < 4; j++)
#pragma unroll
            for (int l = 0; l < 4; l++) acc[i][j][l] = 0.f;

    const int KT = K / BK;
    const int lrow = tid >> 2;        // 0..63
    const int lc4  = (tid & 3) * 4;   // 0,4,8,12
    float4 ra[2], rb[2];

    // prologue: tile 0
    {
        int k0 = 0;
#pragma unroll
        for (int t = 0; t < 2; t++) {
            ra[t] = *(const float4*)(A  + (size_t)(m0 + lrow + t * 64) * lda + k0 + lc4);
            rb[t] = *(const float4*)(Bt + (size_t)(n0 + lrow + t * 64) * ldb + k0 + lc4);
        }
#pragma unroll
        for (int t = 0; t < 2; t++) {
            *(float4*)(As + (lrow + t * 64) * PADA + lc4) = conv4(ra[t]);
            *(float4*)(Bs + (lrow + t * 64) * PADA + lc4) = conv4(rb[t]);
        }
    }
    __syncthreads();

    for (int kt = 0; kt < KT; kt++) {
        if (kt + 1 < KT) {
            int k0 = (kt + 1) * BK;
#pragma unroll
            for (int t = 0; t < 2; t++) {
                ra[t] = *(const float4*)(A  + (size_t)(m0 + lrow + t * 64) * lda + k0 + lc4);
                rb[t] = *(const float4*)(Bt + (size_t)(n0 + lrow + t * 64) * ldb + k0 + lc4);
            }
        }
        // compute current buffer
        {
            const float* sA = As + (kt & 1) * BM * PADA;
            const float* sB = Bs + (kt & 1) * BN * PADA;
#pragma unroll
            for (int kk = 0; kk < BK; kk += 8) {
                unsigned a[4][4], b[4][2];
#pragma unroll
                for (int mi = 0; mi < 4; mi++) {
                    const float* ap = sA + (wm + mi * 16 + gid) * PADA + kk + tig;
                    a[mi][0] = __float_as_uint(ap[0]);
                    a[mi][1] = __float_as_uint(ap[8 * PADA]);
                    a[mi][2] = __float_as_uint(ap[4]);
                    a[mi][3] = __float_as_uint(ap[8 * PADA + 4]);
                }
#pragma unroll
                for (int ni = 0; ni < 4; ni++) {
                    const float* bp = sB + (wn + ni * 8 + gid) * PADA + kk + tig;
                    b[ni][0] = __float_as_uint(bp[0]);
                    b[ni][1] = __float_as_uint(bp[4]);
                }
#pragma unroll
                for (int mi = 0; mi < 4; mi++)
#pragma unroll
                    for (int ni = 0; ni < 4; ni++)
                        mma8(acc[mi][ni], a[mi], b[ni][0], b[ni][1]);
            }
        }
        if (kt + 1 < KT) {
            float* dA = As + ((kt + 1) & 1) * BM * PADA;
            float* dB = Bs + ((kt + 1) & 1) * BN * PADA;
#pragma unroll
            for (int t = 0; t < 2; t++) {
                *(float4*)(dA + (lrow + t * 64) * PADA + lc4) = conv4(ra[t]);
                *(float4*)(dB + (lrow + t * 64) * PADA + lc4) = conv4(rb[t]);
            }
        }
        __syncthreads();
    }

    // epilogue
#pragma unroll
    for (int mi = 0; mi < 4; mi++) {
        int r0 = m0 + wm + mi * 16 + gid;
#pragma unroll
        for (int ni = 0; ni < 4; ni++) {
            int c0 = n0 + wn + ni * 8 + 2 * tig;
            float bb0 = bias ? bias[c0]     : 0.f;
            float bb1 = bias ? bias[c0 + 1] : 0.f;
            float2 v0 = make_float2(acc[mi][ni][0] * alpha + bb0,
                                    acc[mi][ni][1] * alpha + bb1);
            float2 v1 = make_float2(acc[mi][ni][2] * alpha + bb0,
                                    acc[mi][ni][3] * alpha + bb1);
            *(float2*)(C + (size_t)r0 * ldc + c0)       = v0;
            *(float2*)(C + (size_t)(r0 + 8) * ldc + c0) = v1;
        }
    }
}

// ---------------- C = A * B, A[M,K] rm, B[K,N] rm ----------------
__device__ __forceinline__ void gemm_abn_body(
    const float* __restrict__ A, const float* __restrict__ B,
    float* __restrict__ C, int K, int lda, int ldb, int ldc)
{
    extern __shared__ float smem[];
    float* As = smem;                 // [2][BM*PADA]
    float* Bs = smem + 2 * BM * PADA; // [2][BK*PADB]

    const int tid  = threadIdx.x;
    const int lane = tid & 31;
    const int warp = tid >> 5;
    const int gid  = lane >> 2;
    const int tig  = lane & 3;
    const int wm   = (warp & 1) * 64;
    const int wn   = (warp >> 1) * 32;
    const int m0 = blockIdx.x * BM, n0 = blockIdx.y * BN;

    float acc[4][4][4];
#pragma unroll
    for (int i = 0; i < 4; i++)
#pragma unroll
        for (int j = 0; j < 4; j++)
#pragma unroll
            for (int l = 0; l < 4; l++) acc[i][j][l] = 0.f;

    const int KT = K / BK;
    const int lrow = tid >> 2;
    const int lc4  = (tid & 3) * 4;
    const int bn4  = (tid & 31) * 4;  // float col in B tile
    const int bk   = tid >> 5;        // 0..7
    float4 ra[2], rb[2];

    {
        int k0 = 0;
#pragma unroll
        for (int t = 0; t < 2; t++) {
            ra[t] = *(const float4*)(A + (size_t)(m0 + lrow + t * 64) * lda + k0 + lc4);
            rb[t] = *(const float4*)(B + (size_t)(k0 + bk + t * 8) * ldb + n0 + bn4);
        }
#pragma unroll
        for (int t = 0; t < 2; t++) {
            *(float4*)(As + (lrow + t * 64) * PADA + lc4) = conv4(ra[t]);
            *(float4*)(Bs + (bk + t * 8) * PADB + bn4)    = conv4(rb[t]);
        }
    }
    __syncthreads();

    for (int kt = 0; kt < KT; kt++) {
        if (kt + 1 < KT) {
            int k0 = (kt + 1) * BK;
#pragma unroll
            for (int t = 0; t < 2; t++) {
                ra[t] = *(const float4*)(A + (size_t)(m0 + lrow + t * 64) * lda + k0 + lc4);
                rb[t] = *(const float4*)(B + (size_t)(k0 + bk + t * 8) * ldb + n0 + bn4);
            }
        }
        {
            const float* sA = As + (kt & 1) * BM * PADA;
            const float* sB = Bs + (kt & 1) * BK * PADB;
#pragma unroll
            for (int kk = 0; kk < BK; kk += 8) {
                unsigned a[4][4], b[4][2];
#pragma unroll
                for (int mi = 0; mi < 4; mi++) {
                    const float* ap = sA + (wm + mi * 16 + gid) * PADA + kk + tig;
                    a[mi][0] = __float_as_uint(ap[0]);
                    a[mi][1] = __float_as_uint(ap[8 * PADA]);
                    a[mi][2] = __float_as_uint(ap[4]);
                    a[mi][3] = __float_as_uint(ap[8 * PADA + 4]);
                }
#pragma unroll
                for (int ni = 0; ni < 4; ni++) {
                    const float* bp = sB + (kk + tig) * PADB + wn + ni * 8 + gid;
                    b[ni][0] = __float_as_uint(bp[0]);
                    b[ni][1] = __float_as_uint(bp[4 * PADB]);
                }
#pragma unroll
                for (int mi = 0; mi < 4; mi++)
#pragma unroll
                    for (int ni = 0; ni < 4; ni++)
                        mma8(acc[mi][ni], a[mi], b[ni][0], b[ni][1]);
            }
        }
        if (kt + 1 < KT) {
            float* dA = As + ((kt + 1) & 1) * BM * PADA;
            float* dB = Bs + ((kt + 1) & 1) * BK * PADB;
#pragma unroll
            for (int t = 0; t < 2; t++) {
                *(float4*)(dA + (lrow + t * 64) * PADA + lc4) = conv4(ra[t]);
                *(float4*)(dB + (bk + t * 8) * PADB + bn4)    = conv4(rb[t]);
            }
        }
        __syncthreads();
    }

#pragma unroll
    for (int mi = 0; mi < 4; mi++) {
        int r0 = m0 + wm + mi * 16 + gid;
#pragma unroll
        for (int ni = 0; ni < 4; ni++) {
            int c0 = n0 + wn + ni * 8 + 2 * tig;
            float2 v0 = make_float2(acc[mi][ni][0], acc[mi][ni][1]);
            float2 v1 = make_float2(acc[mi][ni][2], acc[mi][ni][3]);
            *(float2*)(C + (size_t)r0 * ldc + c0)       = v0;
            *(float2*)(C + (size_t)(r0 + 8) * ldc + c0) = v1;
        }
    }
}

// ---------------- kernels ----------------
__global__ void __launch_bounds__(256) qkv_kernel(
    const float* __restrict__ x,
    const float* __restrict__ Wq, const float* __restrict__ bq,
    const float* __restrict__ Wk, const float* __restrict__ bk,
    const float* __restrict__ Wv, const float* __restrict__ bv)
{
    int z = blockIdx.z;
    const float* W = (z == 0) ? Wq : (z == 1) ? Wk : Wv;
    const float* b = (z == 0) ? bq : (z == 1) ? bk : bv;
    float* out     = (z == 0) ? g_q : (z == 1) ? g_k : g_v;
    gemm_abt_body(x, W, out, b, HID, HID, HID, HID, 1.0f);
}

__global__ void __launch_bounds__(256) scores_kernel()
{
    int z = blockIdx.z;
    const float scale = 0.036084391824351615f; // 1/sqrt(768)
    gemm_abt_body(g_q + (size_t)z * SEQ * HID,
                  g_k + (size_t)z * SEQ * HID,
                  g_s + (size_t)z * SEQ * SEQ,
                  nullptr, HID, HID, HID, SEQ, scale);
}

__global__ void __launch_bounds__(256) softmax_kernel()
{
    __shared__ float red[8];
    const int row = blockIdx.x;
    float* p = g_s + (size_t)row * SEQ;
    const int tid = threadIdx.x;

    float v[16];
    float mx = -__int_as_float(0x7f800000);
#pragma unroll
    for (int i = 0; i < 4; i++) {
        float4 t = *(const float4*)(p + (size_t)(tid + i * 256) * 4);
        v[i * 4 + 0] = t.x; v[i * 4 + 1] = t.y; v[i * 4 + 2] = t.z; v[i * 4 + 3] = t.w;
        mx = fmaxf(mx, fmaxf(fmaxf(t.x, t.y), fmaxf(t.z, t.w)));
    }
#pragma unroll
    for (int o = 16; o; o >>= 1) mx = fmaxf(mx, __shfl_xor_sync(0xffffffffu, mx, o));
    if ((tid & 31) == 0) red[tid >> 5] = mx;
    __syncthreads();
    float bm = red[0];
#pragma unroll
    for (int i = 1; i < 8; i++) bm = fmaxf(bm, red[i]);

    float sum = 0.f;
#pragma unroll
    for (int i = 0; i < 16; i++) { v[i] = __expf(v[i] - bm); sum += v[i]; }
#pragma unroll
    for (int o = 16; o; o >>= 1) sum += __shfl_xor_sync(0xffffffffu, sum, o);
    __syncthreads();
    if ((tid & 31) == 0) red[tid >> 5] = sum;
    __syncthreads();
    float bs = 0.f;
#pragma unroll
    for (int i = 0; i < 8; i++) bs += red[i];
    float inv = 1.0f / bs;

#pragma unroll
    for (int i = 0; i < 4; i++) {
        float4 t = make_float4(v[i * 4 + 0] * inv, v[i * 4 + 1] * inv,
                               v[i * 4 + 2] * inv, v[i * 4 + 3] * inv);
        *(float4*)(p + (size_t)(tid + i * 256) * 4) = t;
    }
}

__global__ void __launch_bounds__(256) av_kernel(float* __restrict__ out)
{
    int z = blockIdx.z;
    gemm_abn_body(g_s + (size_t)z * SEQ * SEQ,
                  g_v + (size_t)z * SEQ * HID,
                  out + (size_t)z * SEQ * HID,
                  SEQ, SEQ, HID, HID);
}

// ---------------- launch ----------------
extern "C" void kernel_launch(void* const* d_in, const int* in_sizes, int n_in,
                              void* d_out, int out_size)
{
    const float* x  = (const float*)d_in[0];
    const float* Wq = (const float*)d_in[1];
    const float* bq = (const float*)d_in[2];
    const float* Wk = (const float*)d_in[3];
    const float* bk = (const float*)d_in[4];
    const float* Wv = (const float*)d_in[5];
    const float* bv = (const float*)d_in[6];
    float* out = (float*)d_out;

    size_t smem_abt = (size_t)(2 * BM * PADA + 2 * BN * PADA) * sizeof(float); // 40960 B
    size_t smem_abn = (size_t)(2 * BM * PADA + 2 * BK * PADB) * sizeof(float); // 37888 B

    dim3 blk(256);
    qkv_kernel<<<dim3(MTOT / BM, HID / BN, 3), blk, smem_abt>>>(x, Wq, bq, Wk, bk, Wv, bv);
    scores_kernel<<<dim3(SEQ / BM, SEQ / BN, BATCH), blk, smem_abt>>>();
    softmax_kernel<<<dim3(MTOT), blk>>>();
    av_kernel<<<dim3(SEQ / BM, HID / BN, BATCH), blk, smem_abn>>>(out);
}

// round 5
// speedup vs baseline: 1.1539x; 1.1539x over previous
#include <cuda_runtime.h>
#include <math.h>
#include <stdint.h>

#define HID   768
#define SEQ   4096
#define BATCH 4
#define MTOT  (BATCH*SEQ)   // 16384

#define BM 128
#define BN 128
#define BK 16
#define NSTG 4
#define PADA 20    // floats per row (16 data + 4 pad), 80B
#define PADB 136   // floats per row for ABN B tile, 544B

#define ABT_STAGE 20480
#define ABT_BOFF  10240
#define ABT_SMEM  (NSTG*ABT_STAGE)   // 81920
#define ABN_STAGE 18944
#define ABN_BOFF  10240
#define ABN_SMEM  (NSTG*ABN_STAGE)   // 75776

// ---------------- scratch ----------------
__device__ float g_q[(size_t)MTOT * HID];
__device__ float g_k[(size_t)MTOT * HID];
__device__ float g_v[(size_t)MTOT * HID];
__device__ float g_s[(size_t)BATCH * SEQ * SEQ];

// ---------------- helpers ----------------
__device__ __forceinline__ uint32_t smem_u32(const void* p) {
    uint32_t a;
    asm("{ .reg .u64 t; cvta.to.shared.u64 t, %1; cvt.u32.u64 %0, t; }" : "=r"(a) : "l"(p));
    return a;
}
__device__ __forceinline__ void cp16(uint32_t dst, const void* src) {
    asm volatile("cp.async.cg.shared.global [%0], [%1], 16;" :: "r"(dst), "l"(src));
}
__device__ __forceinline__ void cp_commit() {
    asm volatile("cp.async.commit_group;" ::: "memory");
}
template<int N> __device__ __forceinline__ void cp_wait() {
    asm volatile("cp.async.wait_group %0;" :: "n"(N) : "memory");
}
// round-to-nearest tf32 bits from fp32 (de-biases HMMA's truncation)
__device__ __forceinline__ unsigned f2tf(float x) {
    unsigned y; asm("cvt.rna.tf32.f32 %0, %1;" : "=r"(y) : "f"(x)); return y;
}
__device__ __forceinline__ void mma8(float* c, const unsigned* a, unsigned b0, unsigned b1) {
    asm volatile(
        "mma.sync.aligned.m16n8k8.row.col.f32.tf32.tf32.f32 "
        "{%0,%1,%2,%3}, {%4,%5,%6,%7}, {%8,%9}, {%0,%1,%2,%3};"
        : "+f"(c[0]), "+f"(c[1]), "+f"(c[2]), "+f"(c[3])
        : "r"(a[0]), "r"(a[1]), "r"(a[2]), "r"(a[3]), "r"(b0), "r"(b1));
}

// ---------------- compute cores (fragments RN-converted after LDS) ----------------
__device__ __forceinline__ void compute_stage(
    const float* sA, const float* sB, float acc[4][4][4],
    int wm, int wn, int gid, int tig)
{
#pragma unroll
    for (int kk = 0; kk < BK; kk += 8) {
        unsigned a[4][4], b[4][2];
#pragma unroll
        for (int mi = 0; mi < 4; mi++) {
            const float* ap = sA + (wm + mi * 16 + gid) * PADA + kk + tig;
            a[mi][0] = f2tf(ap[0]);
            a[mi][1] = f2tf(ap[8 * PADA]);
            a[mi][2] = f2tf(ap[4]);
            a[mi][3] = f2tf(ap[8 * PADA + 4]);
        }
#pragma unroll
        for (int ni = 0; ni < 4; ni++) {
            const float* bp = sB + (wn + ni * 8 + gid) * PADA + kk + tig;
            b[ni][0] = f2tf(bp[0]);
            b[ni][1] = f2tf(bp[4]);
        }
#pragma unroll
        for (int mi = 0; mi < 4; mi++)
#pragma unroll
            for (int ni = 0; ni < 4; ni++)
                mma8(acc[mi][ni], a[mi], b[ni][0], b[ni][1]);
    }
}
__device__ __forceinline__ void compute_stage_bn(
    const float* sA, const float* sB, float acc[4][4][4],
    int wm, int wn, int gid, int tig)
{
#pragma unroll
    for (int kk = 0; kk < BK; kk += 8) {
        unsigned a[4][4], b[4][2];
#pragma unroll
        for (int mi = 0; mi < 4; mi++) {
            const float* ap = sA + (wm + mi * 16 + gid) * PADA + kk + tig;
            a[mi][0] = f2tf(ap[0]);
            a[mi][1] = f2tf(ap[8 * PADA]);
            a[mi][2] = f2tf(ap[4]);
            a[mi][3] = f2tf(ap[8 * PADA + 4]);
        }
#pragma unroll
        for (int ni = 0; ni < 4; ni++) {
            const float* bp = sB + (kk + tig) * PADB + wn + ni * 8 + gid;
            b[ni][0] = f2tf(bp[0]);
            b[ni][1] = f2tf(bp[4 * PADB]);
        }
#pragma unroll
        for (int mi = 0; mi < 4; mi++)
#pragma unroll
            for (int ni = 0; ni < 4; ni++)
                mma8(acc[mi][ni], a[mi], b[ni][0], b[ni][1]);
    }
}

__device__ __forceinline__ void store_epilogue(
    float* __restrict__ C, const float* __restrict__ bias,
    float acc[4][4][4], int m0, int n0, int ldc, float alpha,
    int wm, int wn, int gid, int tig)
{
#pragma unroll
    for (int mi = 0; mi < 4; mi++) {
        int r0 = m0 + wm + mi * 16 + gid;
#pragma unroll
        for (int ni = 0; ni < 4; ni++) {
            int c0 = n0 + wn + ni * 8 + 2 * tig;
            float bb0 = bias ? bias[c0]     : 0.f;
            float bb1 = bias ? bias[c0 + 1] : 0.f;
            float2 v0 = make_float2(acc[mi][ni][0] * alpha + bb0,
                                    acc[mi][ni][1] * alpha + bb1);
            float2 v1 = make_float2(acc[mi][ni][2] * alpha + bb0,
                                    acc[mi][ni][3] * alpha + bb1);
            *(float2*)(C + (size_t)r0 * ldc + c0)       = v0;
            *(float2*)(C + (size_t)(r0 + 8) * ldc + c0) = v1;
        }
    }
}

// ---------------- C = alpha * A * Bt^T (+bias), cp.async 4-stage ----------------
__device__ __forceinline__ void gemm_abt_body(
    const float* __restrict__ A, const float* __restrict__ Bt,
    float* __restrict__ C, const float* __restrict__ bias,
    int K, int lda, int ldb, int ldc, float alpha)
{
    extern __shared__ char smem[];
    const uint32_t sb = smem_u32(smem);

    const int tid  = threadIdx.x;
    const int lane = tid & 31;
    const int warp = tid >> 5;
    const int gid  = lane >> 2;
    const int tig  = lane & 3;
    const int wm   = (warp & 1) * 64;
    const int wn   = (warp >> 1) * 32;
    const int m0 = blockIdx.x * BM, n0 = blockIdx.y * BN;

    float acc[4][4][4];
#pragma unroll
    for (int i = 0; i < 4; i++)
#pragma unroll
        for (int j = 0; j < 4; j++)
#pragma unroll
            for (int l = 0; l < 4; l++) acc[i][j][l] = 0.f;

    const int KT = K / BK;
    const int r  = tid >> 2;
    const int ch = tid & 3;

#pragma unroll
    for (int s = 0; s < NSTG - 1; s++) {
        const int k0 = s * BK;
        const uint32_t st = sb + s * ABT_STAGE;
#pragma unroll
        for (int i = 0; i < 2; i++) {
            int rr = r + i * 64;
            cp16(st + rr * 80 + ch * 16, A  + (size_t)(m0 + rr) * lda + k0 + ch * 4);
            cp16(st + ABT_BOFF + rr * 80 + ch * 16, Bt + (size_t)(n0 + rr) * ldb + k0 + ch * 4);
        }
        cp_commit();
    }

    for (int kt = 0; kt < KT; kt++) {
        if (kt + NSTG - 1 < KT) {
            const int k0 = (kt + NSTG - 1) * BK;
            const uint32_t st = sb + ((kt + NSTG - 1) % NSTG) * ABT_STAGE;
#pragma unroll
            for (int i = 0; i < 2; i++) {
                int rr = r + i * 64;
                cp16(st + rr * 80 + ch * 16, A  + (size_t)(m0 + rr) * lda + k0 + ch * 4);
                cp16(st + ABT_BOFF + rr * 80 + ch * 16, Bt + (size_t)(n0 + rr) * ldb + k0 + ch * 4);
            }
            cp_commit();
            cp_wait<NSTG - 1>();
        } else {
            cp_wait<0>();
        }
        __syncthreads();
        const float* sA = (const float*)(smem + (kt % NSTG) * ABT_STAGE);
        compute_stage(sA, sA + ABT_BOFF / 4, acc, wm, wn, gid, tig);
        __syncthreads();
    }
    store_epilogue(C, bias, acc, m0, n0, ldc, alpha, wm, wn, gid, tig);
}

// ---------------- C = A * B (B row-major [K][N]), cp.async 4-stage ----------------
__device__ __forceinline__ void gemm_abn_body(
    const float* __restrict__ A, const float* __restrict__ B,
    float* __restrict__ C, int K, int lda, int ldb, int ldc)
{
    extern __shared__ char smem[];
    const uint32_t sb = smem_u32(smem);

    const int tid  = threadIdx.x;
    const int lane = tid & 31;
    const int warp = tid >> 5;
    const int gid  = lane >> 2;
    const int tig  = lane & 3;
    const int wm   = (warp & 1) * 64;
    const int wn   = (warp >> 1) * 32;
    const int m0 = blockIdx.x * BM, n0 = blockIdx.y * BN;

    float acc[4][4][4];
#pragma unroll
    for (int i = 0; i < 4; i++)
#pragma unroll
        for (int j = 0; j < 4; j++)
#pragma unroll
            for (int l = 0; l < 4; l++) acc[i][j][l] = 0.f;

    const int KT = K / BK;
    const int r  = tid >> 2;
    const int ch = tid & 3;
    const int br = tid >> 5;
    const int bc = tid & 31;

#pragma unroll
    for (int s = 0; s < NSTG - 1; s++) {
        const int k0 = s * BK;
        const uint32_t st = sb + s * ABN_STAGE;
#pragma unroll
        for (int i = 0; i < 2; i++) {
            int rr = r + i * 64;
            cp16(st + rr * 80 + ch * 16, A + (size_t)(m0 + rr) * lda + k0 + ch * 4);
        }
#pragma unroll
        for (int i = 0; i < 2; i++) {
            int kr = br + i * 8;
            cp16(st + ABN_BOFF + kr * 544 + bc * 16, B + (size_t)(k0 + kr) * ldb + n0 + bc * 4);
        }
        cp_commit();
    }

    for (int kt = 0; kt < KT; kt++) {
        if (kt + NSTG - 1 < KT) {
            const int k0 = (kt + NSTG - 1) * BK;
            const uint32_t st = sb + ((kt + NSTG - 1) % NSTG) * ABN_STAGE;
#pragma unroll
            for (int i = 0; i < 2; i++) {
                int rr = r + i * 64;
                cp16(st + rr * 80 + ch * 16, A + (size_t)(m0 + rr) * lda + k0 + ch * 4);
            }
#pragma unroll
            for (int i = 0; i < 2; i++) {
                int kr = br + i * 8;
                cp16(st + ABN_BOFF + kr * 544 + bc * 16, B + (size_t)(k0 + kr) * ldb + n0 + bc * 4);
            }
            cp_commit();
            cp_wait<NSTG - 1>();
        } else {
            cp_wait<0>();
        }
        __syncthreads();
        const float* sA = (const float*)(smem + (kt % NSTG) * ABN_STAGE);
        compute_stage_bn(sA, sA + ABN_BOFF / 4, acc, wm, wn, gid, tig);
        __syncthreads();
    }
    store_epilogue(C, nullptr, acc, m0, n0, ldc, 1.0f, wm, wn, gid, tig);
}

// ---------------- kernels ----------------
__global__ void __launch_bounds__(256, 2) qkv_kernel(
    const float* __restrict__ x,
    const float* __restrict__ Wq, const float* __restrict__ bq,
    const float* __restrict__ Wk, const float* __restrict__ bk,
    const float* __restrict__ Wv, const float* __restrict__ bv)
{
    int z = blockIdx.z;
    const float* W = (z == 0) ? Wq : (z == 1) ? Wk : Wv;
    const float* b = (z == 0) ? bq : (z == 1) ? bk : bv;
    float* out     = (z == 0) ? g_q : (z == 1) ? g_k : g_v;
    gemm_abt_body(x, W, out, b, HID, HID, HID, HID, 1.0f);
}

__global__ void __launch_bounds__(256, 2) scores_kernel()
{
    int z = blockIdx.z;
    gemm_abt_body(g_q + (size_t)z * SEQ * HID,
                  g_k + (size_t)z * SEQ * HID,
                  g_s + (size_t)z * SEQ * SEQ,
                  nullptr, HID, HID, HID, SEQ, 0.036084391824351615f);
}

__global__ void __launch_bounds__(256, 2) av_kernel(float* __restrict__ out)
{
    int z = blockIdx.z;
    gemm_abn_body(g_s + (size_t)z * SEQ * SEQ,
                  g_v + (size_t)z * SEQ * HID,
                  out + (size_t)z * SEQ * HID,
                  SEQ, SEQ, HID, HID);
}

__global__ void __launch_bounds__(256) softmax_kernel()
{
    __shared__ float red[8];
    const int row = blockIdx.x;
    float* p = g_s + (size_t)row * SEQ;
    const int tid = threadIdx.x;

    float v[16];
    float mx = -__int_as_float(0x7f800000);
#pragma unroll
    for (int i = 0; i < 4; i++) {
        float4 t = *(const float4*)(p + (size_t)(tid + i * 256) * 4);
        v[i*4+0] = t.x; v[i*4+1] = t.y; v[i*4+2] = t.z; v[i*4+3] = t.w;
        mx = fmaxf(mx, fmaxf(fmaxf(t.x, t.y), fmaxf(t.z, t.w)));
    }
#pragma unroll
    for (int o = 16; o; o >>= 1) mx = fmaxf(mx, __shfl_xor_sync(0xffffffffu, mx, o));
    if ((tid & 31) == 0) red[tid >> 5] = mx;
    __syncthreads();
    float bm = red[0];
#pragma unroll
    for (int i = 1; i < 8; i++) bm = fmaxf(bm, red[i]);

    float sum = 0.f;
#pragma unroll
    for (int i = 0; i < 16; i++) { v[i] = __expf(v[i] - bm); sum += v[i]; }
#pragma unroll
    for (int o = 16; o; o >>= 1) sum += __shfl_xor_sync(0xffffffffu, sum, o);
    __syncthreads();
    if ((tid & 31) == 0) red[tid >> 5] = sum;
    __syncthreads();
    float bs = 0.f;
#pragma unroll
    for (int i = 0; i < 8; i++) bs += red[i];
    float inv = 1.0f / bs;

#pragma unroll
    for (int i = 0; i < 4; i++) {
        float4 t = make_float4(v[i*4+0]*inv, v[i*4+1]*inv, v[i*4+2]*inv, v[i*4+3]*inv);
        *(float4*)(p + (size_t)(tid + i * 256) * 4) = t;
    }
}

// ---------------- launch ----------------
extern "C" void kernel_launch(void* const* d_in, const int* in_sizes, int n_in,
                              void* d_out, int out_size)
{
    const float* x  = (const float*)d_in[0];
    const float* Wq = (const float*)d_in[1];
    const float* bq = (const float*)d_in[2];
    const float* Wk = (const float*)d_in[3];
    const float* bk = (const float*)d_in[4];
    const float* Wv = (const float*)d_in[5];
    const float* bv = (const float*)d_in[6];
    float* out = (float*)d_out;

    cudaFuncSetAttribute(qkv_kernel,    cudaFuncAttributeMaxDynamicSharedMemorySize, ABT_SMEM);
    cudaFuncSetAttribute(scores_kernel, cudaFuncAttributeMaxDynamicSharedMemorySize, ABT_SMEM);
    cudaFuncSetAttribute(av_kernel,     cudaFuncAttributeMaxDynamicSharedMemorySize, ABN_SMEM);

    dim3 blk(256);
    qkv_kernel<<<dim3(MTOT / BM, HID / BN, 3), blk, ABT_SMEM>>>(x, Wq, bq, Wk, bk, Wv, bv);
    scores_kernel<<<dim3(SEQ / BM, SEQ / BN, BATCH), blk, ABT_SMEM>>>();
    softmax_kernel<<<dim3(MTOT), blk>>>();
    av_kernel<<<dim3(SEQ / BM, HID / BN, BATCH), blk, ABN_SMEM>>>(out);
}